// round 4
// baseline (speedup 1.0000x reference)
#include <cuda_runtime.h>

// Problem constants (fixed by the dataset)
#define NN   50000
#define NE   800000
#define NG   64
#define NPAD 50048            // multiple of 128 for unguarded GEMM
#define NEG_SLOPE 0.01f
#define BN_EPS    1e-5f

// ---------------- scratch (static __device__, no allocation) ----------------
__device__ __align__(16) float g_bufA[NPAD * 256];
__device__ __align__(16) float g_bufB[NPAD * 256];
__device__ __align__(16) int   g_csrsrc[NE];
__device__ __align__(16) float g_csrnorm[NE];
__device__ __align__(16) int   g_rowptr[NN + 4];
__device__ __align__(16) int   g_deg[NN];
__device__ __align__(16) int   g_fill[NN];
__device__ __align__(16) float g_dinv[NN];
__device__ __align__(16) float g_selfnorm[NN];
__device__ __align__(16) float g_colsum[256];
__device__ __align__(16) float g_colsumsq[256];
__device__ __align__(16) float g_alpha[256];
__device__ __align__(16) float g_beta[256];
__device__ __align__(16) float g_Wfold[256 * 256];
__device__ __align__(16) float g_bconst[256];
__device__ __align__(16) float g_zerovec[256];     // never written -> stays 0
__device__ __align__(16) float g_pool[NG * 128];
__device__ __align__(16) int   g_counts[NG];

// ---------------- small utility kernels ----------------
__global__ void copy_x_kernel(const float* __restrict__ x) {
    int i = blockIdx.x * blockDim.x + threadIdx.x;
    if (i < NN * 128) g_bufA[i] = x[i];
}

__global__ void zero_misc_kernel() {
    int i = blockIdx.x * blockDim.x + threadIdx.x;
    if (i < NN) { g_deg[i] = 0; g_fill[i] = 0; }
    if (i < NG * 128) g_pool[i] = 0.f;
    if (i < NG) g_counts[i] = 0;
}

__global__ void zero_stats_kernel() {
    int t = threadIdx.x;
    g_colsum[t] = 0.f;
    g_colsumsq[t] = 0.f;
}

// edge_index is int32 (JAX x64 disabled downcasts int64 -> int32)
__global__ void deg_kernel(const int* __restrict__ ei) {
    int e = blockIdx.x * blockDim.x + threadIdx.x;
    if (e < NE) atomicAdd(&g_deg[ei[NE + e]], 1);  // dst row
}

__global__ void prep_kernel() {
    int i = blockIdx.x * blockDim.x + threadIdx.x;
    if (i < NN) {
        float d = (float)(g_deg[i] + 1);
        g_dinv[i] = rsqrtf(d);
        g_selfnorm[i] = 1.0f / d;
    }
}

// exclusive scan of g_deg -> g_rowptr (single block, 1024 threads)
__global__ void scan_kernel() {
    __shared__ int sh[1024];
    __shared__ int base_s;
    int tid = threadIdx.x;
    if (tid == 0) base_s = 0;
    __syncthreads();
    for (int start = 0; start < NN; start += 1024) {
        int i = start + tid;
        int v = (i < NN) ? g_deg[i] : 0;
        sh[tid] = v;
        __syncthreads();
        for (int off = 1; off < 1024; off <<= 1) {
            int add = (tid >= off) ? sh[tid - off] : 0;
            __syncthreads();
            sh[tid] += add;
            __syncthreads();
        }
        if (i < NN) g_rowptr[i] = base_s + sh[tid] - v;
        __syncthreads();
        if (tid == 0) base_s += sh[1023];
        __syncthreads();
    }
    if (tid == 0) g_rowptr[NN] = base_s;
}

__global__ void scatter_kernel(const int* __restrict__ ei) {
    int e = blockIdx.x * blockDim.x + threadIdx.x;
    if (e < NE) {
        int s = ei[e];
        int d = ei[NE + e];
        int p = g_rowptr[d] + atomicAdd(&g_fill[d], 1);
        g_csrsrc[p] = s;
        g_csrnorm[p] = g_dinv[s] * g_dinv[d];
    }
}

// ---------------- GEMM: C[M,Nn] = A[M,K] @ W[K,Nn] + bconst (row bcast) -----
// 128x128 block tile, BK=16, 256 threads, 8x8 per thread (4+4 split)
__global__ __launch_bounds__(256)
void gemm_kernel(const float* __restrict__ A, const float* __restrict__ W,
                 const float* __restrict__ bconst, float* __restrict__ C,
                 int K, int Nn) {
    const int BM = 128, BN = 128, BK = 16;
    __shared__ __align__(16) float As[BK * BM];
    __shared__ __align__(16) float Bs[BK * BN];
    const int tid = threadIdx.x;
    const float* Ab = A + (size_t)blockIdx.y * BM * K;
    const float* Wb = W + blockIdx.x * BN;
    float* Cb = C + (size_t)blockIdx.y * BM * Nn + blockIdx.x * BN;
    const int tr = tid >> 4;            // 0..15
    const int tc = tid & 15;            // 0..15
    const int arow = tid >> 2;          // 0..63
    const int acol = (tid & 3) << 2;    // 0,4,8,12
    const int brow = tid >> 5;          // 0..7
    const int bcol = (tid & 31) << 2;   // 0..124

    float acc[8][8];
#pragma unroll
    for (int i = 0; i < 8; i++)
#pragma unroll
        for (int j = 0; j < 8; j++) acc[i][j] = 0.f;

    for (int k0 = 0; k0 < K; k0 += BK) {
        float4 a0 = *(const float4*)(Ab + (size_t)arow * K + k0 + acol);
        float4 a1 = *(const float4*)(Ab + (size_t)(arow + 64) * K + k0 + acol);
        float4 b0 = *(const float4*)(Wb + (size_t)(k0 + brow) * Nn + bcol);
        float4 b1 = *(const float4*)(Wb + (size_t)(k0 + brow + 8) * Nn + bcol);
        __syncthreads();
        As[(acol + 0) * BM + arow] = a0.x;
        As[(acol + 1) * BM + arow] = a0.y;
        As[(acol + 2) * BM + arow] = a0.z;
        As[(acol + 3) * BM + arow] = a0.w;
        As[(acol + 0) * BM + arow + 64] = a1.x;
        As[(acol + 1) * BM + arow + 64] = a1.y;
        As[(acol + 2) * BM + arow + 64] = a1.z;
        As[(acol + 3) * BM + arow + 64] = a1.w;
        *(float4*)(Bs + brow * BN + bcol) = b0;
        *(float4*)(Bs + (brow + 8) * BN + bcol) = b1;
        __syncthreads();
#pragma unroll
        for (int k = 0; k < BK; k++) {
            float rm[8], rn[8];
            *(float4*)(rm)     = *(const float4*)(As + k * BM + (tr << 2));
            *(float4*)(rm + 4) = *(const float4*)(As + k * BM + (tr << 2) + 64);
            *(float4*)(rn)     = *(const float4*)(Bs + k * BN + (tc << 2));
            *(float4*)(rn + 4) = *(const float4*)(Bs + k * BN + (tc << 2) + 64);
#pragma unroll
            for (int i = 0; i < 8; i++)
#pragma unroll
                for (int j = 0; j < 8; j++)
                    acc[i][j] = fmaf(rm[i], rn[j], acc[i][j]);
        }
    }

    float bc[8];
#pragma unroll
    for (int j = 0; j < 4; j++) {
        bc[j]     = bconst[blockIdx.x * BN + (tc << 2) + j];
        bc[j + 4] = bconst[blockIdx.x * BN + (tc << 2) + 64 + j];
    }
#pragma unroll
    for (int i = 0; i < 8; i++) {
        int row = (tr << 2) + ((i < 4) ? i : (60 + i));
        float4 lo, hi;
        lo.x = acc[i][0] + bc[0]; lo.y = acc[i][1] + bc[1];
        lo.z = acc[i][2] + bc[2]; lo.w = acc[i][3] + bc[3];
        hi.x = acc[i][4] + bc[4]; hi.y = acc[i][5] + bc[5];
        hi.z = acc[i][6] + bc[6]; hi.w = acc[i][7] + bc[7];
        *(float4*)(Cb + (size_t)row * Nn + (tc << 2)) = lo;
        *(float4*)(Cb + (size_t)row * Nn + (tc << 2) + 64) = hi;
    }
}

// ---------------- aggregation + bias + LeakyReLU + BN-stat partials --------
template <int DO>
__global__ void agg_kernel(const float* __restrict__ hw,
                           const float* __restrict__ bias,
                           float* __restrict__ out) {
    const int t = threadIdx.x;           // one thread per feature
    const int NPB = 32;
    int n0 = blockIdx.x * NPB;
    int n1 = min(n0 + NPB, NN);
    float s = 0.f, ss = 0.f;
    float b = bias[t];
    for (int n = n0; n < n1; ++n) {
        int e0 = g_rowptr[n], e1 = g_rowptr[n + 1];
        float acc = 0.f;
        int e = e0;
        for (; e + 4 <= e1; e += 4) {
            int s0 = g_csrsrc[e], s1 = g_csrsrc[e + 1];
            int s2 = g_csrsrc[e + 2], s3 = g_csrsrc[e + 3];
            float w0 = g_csrnorm[e], w1 = g_csrnorm[e + 1];
            float w2 = g_csrnorm[e + 2], w3 = g_csrnorm[e + 3];
            float v0 = hw[(size_t)s0 * DO + t];
            float v1 = hw[(size_t)s1 * DO + t];
            float v2 = hw[(size_t)s2 * DO + t];
            float v3 = hw[(size_t)s3 * DO + t];
            acc = fmaf(v0, w0, acc);
            acc = fmaf(v1, w1, acc);
            acc = fmaf(v2, w2, acc);
            acc = fmaf(v3, w3, acc);
        }
        for (; e < e1; ++e)
            acc = fmaf(hw[(size_t)g_csrsrc[e] * DO + t], g_csrnorm[e], acc);
        float v = fmaf(hw[(size_t)n * DO + t], g_selfnorm[n], acc) + b;
        v = (v > 0.f) ? v : NEG_SLOPE * v;
        out[(size_t)n * DO + t] = v;
        s += v;
        ss = fmaf(v, v, ss);
    }
    atomicAdd(&g_colsum[t], s);
    atomicAdd(&g_colsumsq[t], ss);
}

__global__ void stats_kernel(const float* __restrict__ g,
                             const float* __restrict__ bt) {
    int t = threadIdx.x;
    float mu = g_colsum[t] * (1.0f / NN);
    float var = g_colsumsq[t] * (1.0f / NN) - mu * mu;
    var = fmaxf(var, 0.f);
    float a = g[t] * rsqrtf(var + BN_EPS);
    g_alpha[t] = a;
    g_beta[t] = bt[t] - mu * a;
}

// Wfold[k,j] = alpha[k]*W[k,j]; bconst[j] = sum_k beta[k]*W[k,j]
__global__ void fold_kernel(const float* __restrict__ W, int K, int Nn) {
    int j = threadIdx.x;
    if (j >= Nn) return;
    float bc = 0.f;
    for (int k = 0; k < K; k++) {
        float w = W[k * Nn + j];
        g_Wfold[k * Nn + j] = g_alpha[k] * w;
        bc = fmaf(g_beta[k], w, bc);
    }
    g_bconst[j] = bc;
}

// ---------------- pooling ----------------
__global__ void counts_kernel(const int* __restrict__ batch) {
    int i = blockIdx.x * blockDim.x + threadIdx.x;
    if (i < NN) atomicAdd(&g_counts[batch[i]], 1);
}

__global__ void pool_kernel(const float* __restrict__ h,
                            const int* __restrict__ batch) {
    const int t = threadIdx.x;   // 128
    const int CH = 128;
    int n0 = blockIdx.x * CH;
    int n1 = min(n0 + CH, NN);
    int cur = batch[n0];
    float acc = 0.f;
    for (int n = n0; n < n1; n++) {
        int gr = batch[n];
        if (gr != cur) {
            atomicAdd(&g_pool[cur * 128 + t], acc);
            acc = 0.f;
            cur = gr;
        }
        acc += h[(size_t)n * 128 + t];
    }
    atomicAdd(&g_pool[cur * 128 + t], acc);
}

__global__ void finalize_kernel(float* __restrict__ out) {
    int gr = blockIdx.x, t = threadIdx.x;
    float c = fmaxf((float)g_counts[gr], 1.0f);
    out[gr * 128 + t] = g_alpha[t] * (g_pool[gr * 128 + t] / c) + g_beta[t];
}

// ---------------- launch ----------------
extern "C" void kernel_launch(void* const* d_in, const int* in_sizes, int n_in,
                              void* d_out, int out_size) {
    const float* x = (const float*)d_in[0];
    const int* ei = (const int*)d_in[1];      // int32 (JAX x64 disabled)
    const int* batch = (const int*)d_in[2];   // int32
    const float* W1 = (const float*)d_in[3];
    const float* b1 = (const float*)d_in[4];
    const float* g1 = (const float*)d_in[5];
    const float* bt1 = (const float*)d_in[6];
    const float* W2 = (const float*)d_in[7];
    const float* b2 = (const float*)d_in[8];
    const float* g2 = (const float*)d_in[9];
    const float* bt2 = (const float*)d_in[10];
    const float* W3 = (const float*)d_in[11];
    const float* b3 = (const float*)d_in[12];
    const float* g3 = (const float*)d_in[13];
    const float* bt3 = (const float*)d_in[14];
    const float* W4 = (const float*)d_in[15];
    const float* b4 = (const float*)d_in[16];
    const float* g4 = (const float*)d_in[17];
    const float* bt4 = (const float*)d_in[18];
    float* out = (float*)d_out;

    float* bufA; cudaGetSymbolAddress((void**)&bufA, g_bufA);
    float* bufB; cudaGetSymbolAddress((void**)&bufB, g_bufB);
    float* Wfold; cudaGetSymbolAddress((void**)&Wfold, g_Wfold);
    float* bconst; cudaGetSymbolAddress((void**)&bconst, g_bconst);
    float* zerovec; cudaGetSymbolAddress((void**)&zerovec, g_zerovec);

    // graph structure (recomputed every call; same work each call)
    copy_x_kernel<<<(NN * 128 + 255) / 256, 256>>>(x);
    zero_misc_kernel<<<(NN + 255) / 256, 256>>>();
    deg_kernel<<<(NE + 255) / 256, 256>>>(ei);
    prep_kernel<<<(NN + 255) / 256, 256>>>();
    scan_kernel<<<1, 1024>>>();
    scatter_kernel<<<(NE + 255) / 256, 256>>>(ei);

    dim3 gemm_grid_256(2, NPAD / 128);
    dim3 gemm_grid_128(1, NPAD / 128);
    int agg_grid = (NN + 31) / 32;

    // ---- layer 1: K=128 -> 256 ----
    gemm_kernel<<<gemm_grid_256, 256>>>(bufA, W1, zerovec, bufB, 128, 256);
    zero_stats_kernel<<<1, 256>>>();
    agg_kernel<256><<<agg_grid, 256>>>(bufB, b1, bufA);
    stats_kernel<<<1, 256>>>(g1, bt1);
    fold_kernel<<<1, 256>>>(W2, 256, 256);

    // ---- layer 2: 256 -> 256 ----
    gemm_kernel<<<gemm_grid_256, 256>>>(bufA, Wfold, bconst, bufB, 256, 256);
    zero_stats_kernel<<<1, 256>>>();
    agg_kernel<256><<<agg_grid, 256>>>(bufB, b2, bufA);
    stats_kernel<<<1, 256>>>(g2, bt2);
    fold_kernel<<<1, 256>>>(W3, 256, 256);

    // ---- layer 3: 256 -> 256 ----
    gemm_kernel<<<gemm_grid_256, 256>>>(bufA, Wfold, bconst, bufB, 256, 256);
    zero_stats_kernel<<<1, 256>>>();
    agg_kernel<256><<<agg_grid, 256>>>(bufB, b3, bufA);
    stats_kernel<<<1, 256>>>(g3, bt3);
    fold_kernel<<<1, 128>>>(W4, 256, 128);

    // ---- layer 4: 256 -> 128 ----
    gemm_kernel<<<gemm_grid_128, 256>>>(bufA, Wfold, bconst, bufB, 256, 128);
    zero_stats_kernel<<<1, 256>>>();
    agg_kernel<128><<<agg_grid, 128>>>(bufB, b4, bufA);
    stats_kernel<<<1, 128>>>(g4, bt4);

    // ---- pooling ----
    counts_kernel<<<(NN + 255) / 256, 256>>>(batch);
    pool_kernel<<<(NN + 127) / 128, 128>>>(bufA, batch);
    finalize_kernel<<<NG, 128>>>(out);
    (void)in_sizes; (void)n_in; (void)out_size;
}

// round 5
// speedup vs baseline: 1.4600x; 1.4600x over previous
#include <cuda_runtime.h>

// Problem constants (fixed by the dataset)
#define NN   50000
#define NE   800000
#define NG   64
#define NPAD 50048            // multiple of 128 for unguarded GEMM
#define NEG_SLOPE 0.01f
#define BN_EPS    1e-5f

// ---------------- scratch (static __device__, no allocation) ----------------
__device__ __align__(16) float g_bufA[NPAD * 256];
__device__ __align__(16) float g_bufB[NPAD * 256];
__device__ __align__(16) int   g_csrsrc[NE];
__device__ __align__(16) float g_csrnorm[NE];
__device__ __align__(16) int   g_rowptr[NN + 4];
__device__ __align__(16) int   g_deg[NN];
__device__ __align__(16) int   g_fill[NN];
__device__ __align__(16) float g_dinv[NN];
__device__ __align__(16) float g_selfnorm[NN];
__device__ __align__(16) float g_colsum[256];
__device__ __align__(16) float g_colsumsq[256];
__device__ __align__(16) float g_alpha[256];
__device__ __align__(16) float g_beta[256];
__device__ __align__(16) float g_Wfold[256 * 256];
__device__ __align__(16) float g_bconst[256];
__device__ __align__(16) float g_zerovec[256];     // never written -> stays 0
__device__ __align__(16) float g_pool[NG * 128];
__device__ __align__(16) int   g_counts[NG];

// ---------------- small utility kernels ----------------
__global__ void copy_x_kernel(const float* __restrict__ x) {
    int i = blockIdx.x * blockDim.x + threadIdx.x;
    if (i < NN * 128) g_bufA[i] = x[i];
}

__global__ void zero_misc_kernel() {
    int i = blockIdx.x * blockDim.x + threadIdx.x;
    if (i < NN) { g_deg[i] = 0; g_fill[i] = 0; }
    if (i < NG * 128) g_pool[i] = 0.f;
    if (i < NG) g_counts[i] = 0;
}

__global__ void zero_stats_kernel() {
    int t = threadIdx.x;
    g_colsum[t] = 0.f;
    g_colsumsq[t] = 0.f;
}

// edge_index is int32 (JAX x64 disabled downcasts int64 -> int32)
__global__ void deg_kernel(const int* __restrict__ ei) {
    int e = blockIdx.x * blockDim.x + threadIdx.x;
    if (e < NE) atomicAdd(&g_deg[ei[NE + e]], 1);  // dst row
}

__global__ void prep_kernel() {
    int i = blockIdx.x * blockDim.x + threadIdx.x;
    if (i < NN) {
        float d = (float)(g_deg[i] + 1);
        g_dinv[i] = rsqrtf(d);
        g_selfnorm[i] = 1.0f / d;
    }
}

// exclusive scan of g_deg -> g_rowptr (single block, 1024 threads)
__global__ void scan_kernel() {
    __shared__ int sh[1024];
    __shared__ int base_s;
    int tid = threadIdx.x;
    if (tid == 0) base_s = 0;
    __syncthreads();
    for (int start = 0; start < NN; start += 1024) {
        int i = start + tid;
        int v = (i < NN) ? g_deg[i] : 0;
        sh[tid] = v;
        __syncthreads();
        for (int off = 1; off < 1024; off <<= 1) {
            int add = (tid >= off) ? sh[tid - off] : 0;
            __syncthreads();
            sh[tid] += add;
            __syncthreads();
        }
        if (i < NN) g_rowptr[i] = base_s + sh[tid] - v;
        __syncthreads();
        if (tid == 0) base_s += sh[1023];
        __syncthreads();
    }
    if (tid == 0) g_rowptr[NN] = base_s;
}

__global__ void scatter_kernel(const int* __restrict__ ei) {
    int e = blockIdx.x * blockDim.x + threadIdx.x;
    if (e < NE) {
        int s = ei[e];
        int d = ei[NE + e];
        int p = g_rowptr[d] + atomicAdd(&g_fill[d], 1);
        g_csrsrc[p] = s;
        g_csrnorm[p] = g_dinv[s] * g_dinv[d];
    }
}

// ---------------- GEMM: C[M,Nn] = A[M,K] @ W[K,Nn] + bconst (row bcast) -----
// 128x128 block tile, BK=16, 256 threads, 8x8 per thread.
// Double-buffered shared memory, register prefetch, 1 sync per K-tile.
__global__ __launch_bounds__(256, 2)
void gemm_kernel(const float* __restrict__ A, const float* __restrict__ W,
                 const float* __restrict__ bconst, float* __restrict__ C,
                 int K, int Nn) {
    const int BM = 128, BN = 128, BK = 16;
    __shared__ __align__(16) float As[2][BK * BM];
    __shared__ __align__(16) float Bs[2][BK * BN];
    const int tid = threadIdx.x;
    const float* Ab = A + (size_t)blockIdx.y * BM * K;
    const float* Wb = W + blockIdx.x * BN;
    float* Cb = C + (size_t)blockIdx.y * BM * Nn + blockIdx.x * BN;
    const int tr = tid >> 4;            // 0..15
    const int tc = tid & 15;            // 0..15
    const int arow = tid >> 2;          // 0..63
    const int acol = (tid & 3) << 2;    // 0,4,8,12
    const int brow = tid >> 5;          // 0..7
    const int bcol = (tid & 31) << 2;   // 0..124

    float acc[8][8];
#pragma unroll
    for (int i = 0; i < 8; i++)
#pragma unroll
        for (int j = 0; j < 8; j++) acc[i][j] = 0.f;

    // load tile 0
    {
        float4 a0 = *(const float4*)(Ab + (size_t)arow * K + acol);
        float4 a1 = *(const float4*)(Ab + (size_t)(arow + 64) * K + acol);
        float4 b0 = *(const float4*)(Wb + (size_t)brow * Nn + bcol);
        float4 b1 = *(const float4*)(Wb + (size_t)(brow + 8) * Nn + bcol);
        As[0][(acol + 0) * BM + arow] = a0.x;
        As[0][(acol + 1) * BM + arow] = a0.y;
        As[0][(acol + 2) * BM + arow] = a0.z;
        As[0][(acol + 3) * BM + arow] = a0.w;
        As[0][(acol + 0) * BM + arow + 64] = a1.x;
        As[0][(acol + 1) * BM + arow + 64] = a1.y;
        As[0][(acol + 2) * BM + arow + 64] = a1.z;
        As[0][(acol + 3) * BM + arow + 64] = a1.w;
        *(float4*)(&Bs[0][brow * BN + bcol]) = b0;
        *(float4*)(&Bs[0][(brow + 8) * BN + bcol]) = b1;
    }
    __syncthreads();

    const int T = K / BK;
    int p = 0;
    for (int t = 0; t < T; ++t) {
        float4 na0, na1, nb0, nb1;
        const bool has_next = (t + 1 < T);
        if (has_next) {
            int k0 = (t + 1) * BK;
            na0 = *(const float4*)(Ab + (size_t)arow * K + k0 + acol);
            na1 = *(const float4*)(Ab + (size_t)(arow + 64) * K + k0 + acol);
            nb0 = *(const float4*)(Wb + (size_t)(k0 + brow) * Nn + bcol);
            nb1 = *(const float4*)(Wb + (size_t)(k0 + brow + 8) * Nn + bcol);
        }
#pragma unroll
        for (int k = 0; k < BK; k++) {
            float rm[8], rn[8];
            *(float4*)(rm)     = *(const float4*)(&As[p][k * BM + (tr << 2)]);
            *(float4*)(rm + 4) = *(const float4*)(&As[p][k * BM + (tr << 2) + 64]);
            *(float4*)(rn)     = *(const float4*)(&Bs[p][k * BN + (tc << 2)]);
            *(float4*)(rn + 4) = *(const float4*)(&Bs[p][k * BN + (tc << 2) + 64]);
#pragma unroll
            for (int i = 0; i < 8; i++)
#pragma unroll
                for (int j = 0; j < 8; j++)
                    acc[i][j] = fmaf(rm[i], rn[j], acc[i][j]);
        }
        if (has_next) {
            int q = p ^ 1;
            As[q][(acol + 0) * BM + arow] = na0.x;
            As[q][(acol + 1) * BM + arow] = na0.y;
            As[q][(acol + 2) * BM + arow] = na0.z;
            As[q][(acol + 3) * BM + arow] = na0.w;
            As[q][(acol + 0) * BM + arow + 64] = na1.x;
            As[q][(acol + 1) * BM + arow + 64] = na1.y;
            As[q][(acol + 2) * BM + arow + 64] = na1.z;
            As[q][(acol + 3) * BM + arow + 64] = na1.w;
            *(float4*)(&Bs[q][brow * BN + bcol]) = nb0;
            *(float4*)(&Bs[q][(brow + 8) * BN + bcol]) = nb1;
        }
        __syncthreads();
        p ^= 1;
    }

    float bc[8];
#pragma unroll
    for (int j = 0; j < 4; j++) {
        bc[j]     = bconst[blockIdx.x * BN + (tc << 2) + j];
        bc[j + 4] = bconst[blockIdx.x * BN + (tc << 2) + 64 + j];
    }
#pragma unroll
    for (int i = 0; i < 8; i++) {
        int row = (tr << 2) + ((i < 4) ? i : (60 + i));
        float4 lo, hi;
        lo.x = acc[i][0] + bc[0]; lo.y = acc[i][1] + bc[1];
        lo.z = acc[i][2] + bc[2]; lo.w = acc[i][3] + bc[3];
        hi.x = acc[i][4] + bc[4]; hi.y = acc[i][5] + bc[5];
        hi.z = acc[i][6] + bc[6]; hi.w = acc[i][7] + bc[7];
        *(float4*)(Cb + (size_t)row * Nn + (tc << 2)) = lo;
        *(float4*)(Cb + (size_t)row * Nn + (tc << 2) + 64) = hi;
    }
}

// ---------------- aggregation + bias + LeakyReLU + BN-stat partials --------
// float4-vectorized: block = (DO/4) x TY threads, 32 nodes per block.
template <int DO>
__global__ void agg_kernel(const float* __restrict__ hw,
                           const float* __restrict__ bias,
                           float* __restrict__ out) {
    const int TX = DO / 4;            // threads along features (64 or 32)
    const int TY = 256 / TX;          // node lanes (4 or 8)
    const int NPB = 32;
    const int tx = threadIdx.x;       // feature group
    const int ty = threadIdx.y;       // node lane
    const float4* hw4 = (const float4*)hw;
    float4* out4 = (float4*)out;

    __shared__ float ssum[DO];
    __shared__ float ssq[DO];
    {
        int lin = ty * TX + tx;
        if (lin < DO) { ssum[lin] = 0.f; ssq[lin] = 0.f; }
    }
    __syncthreads();

    float4 b4 = *(const float4*)(bias + 4 * tx);
    int n0 = blockIdx.x * NPB;
    int n1 = min(n0 + NPB, NN);

    float s0 = 0.f, s1 = 0.f, s2 = 0.f, s3 = 0.f;
    float q0 = 0.f, q1 = 0.f, q2 = 0.f, q3 = 0.f;

    for (int n = n0 + ty; n < n1; n += TY) {
        int e0 = g_rowptr[n], e1 = g_rowptr[n + 1];
        float4 acc = make_float4(0.f, 0.f, 0.f, 0.f);
        int e = e0;
        for (; e + 4 <= e1; e += 4) {
            int i0 = g_csrsrc[e],     i1 = g_csrsrc[e + 1];
            int i2 = g_csrsrc[e + 2], i3 = g_csrsrc[e + 3];
            float w0 = g_csrnorm[e],     w1 = g_csrnorm[e + 1];
            float w2 = g_csrnorm[e + 2], w3 = g_csrnorm[e + 3];
            float4 v0 = hw4[(size_t)i0 * TX + tx];
            float4 v1 = hw4[(size_t)i1 * TX + tx];
            float4 v2 = hw4[(size_t)i2 * TX + tx];
            float4 v3 = hw4[(size_t)i3 * TX + tx];
            acc.x = fmaf(v0.x, w0, acc.x); acc.y = fmaf(v0.y, w0, acc.y);
            acc.z = fmaf(v0.z, w0, acc.z); acc.w = fmaf(v0.w, w0, acc.w);
            acc.x = fmaf(v1.x, w1, acc.x); acc.y = fmaf(v1.y, w1, acc.y);
            acc.z = fmaf(v1.z, w1, acc.z); acc.w = fmaf(v1.w, w1, acc.w);
            acc.x = fmaf(v2.x, w2, acc.x); acc.y = fmaf(v2.y, w2, acc.y);
            acc.z = fmaf(v2.z, w2, acc.z); acc.w = fmaf(v2.w, w2, acc.w);
            acc.x = fmaf(v3.x, w3, acc.x); acc.y = fmaf(v3.y, w3, acc.y);
            acc.z = fmaf(v3.z, w3, acc.z); acc.w = fmaf(v3.w, w3, acc.w);
        }
        for (; e < e1; ++e) {
            int i = g_csrsrc[e];
            float w = g_csrnorm[e];
            float4 v = hw4[(size_t)i * TX + tx];
            acc.x = fmaf(v.x, w, acc.x); acc.y = fmaf(v.y, w, acc.y);
            acc.z = fmaf(v.z, w, acc.z); acc.w = fmaf(v.w, w, acc.w);
        }
        float sn = g_selfnorm[n];
        float4 hv = hw4[(size_t)n * TX + tx];
        float v0 = fmaf(hv.x, sn, acc.x) + b4.x;
        float v1 = fmaf(hv.y, sn, acc.y) + b4.y;
        float v2 = fmaf(hv.z, sn, acc.z) + b4.z;
        float v3 = fmaf(hv.w, sn, acc.w) + b4.w;
        v0 = (v0 > 0.f) ? v0 : NEG_SLOPE * v0;
        v1 = (v1 > 0.f) ? v1 : NEG_SLOPE * v1;
        v2 = (v2 > 0.f) ? v2 : NEG_SLOPE * v2;
        v3 = (v3 > 0.f) ? v3 : NEG_SLOPE * v3;
        out4[(size_t)n * TX + tx] = make_float4(v0, v1, v2, v3);
        s0 += v0; s1 += v1; s2 += v2; s3 += v3;
        q0 = fmaf(v0, v0, q0); q1 = fmaf(v1, v1, q1);
        q2 = fmaf(v2, v2, q2); q3 = fmaf(v3, v3, q3);
    }

    atomicAdd(&ssum[4 * tx + 0], s0);
    atomicAdd(&ssum[4 * tx + 1], s1);
    atomicAdd(&ssum[4 * tx + 2], s2);
    atomicAdd(&ssum[4 * tx + 3], s3);
    atomicAdd(&ssq[4 * tx + 0], q0);
    atomicAdd(&ssq[4 * tx + 1], q1);
    atomicAdd(&ssq[4 * tx + 2], q2);
    atomicAdd(&ssq[4 * tx + 3], q3);
    __syncthreads();
    {
        int lin = ty * TX + tx;
        if (lin < DO) {
            atomicAdd(&g_colsum[lin], ssum[lin]);
            atomicAdd(&g_colsumsq[lin], ssq[lin]);
        }
    }
}

__global__ void stats_kernel(const float* __restrict__ g,
                             const float* __restrict__ bt) {
    int t = threadIdx.x;
    float mu = g_colsum[t] * (1.0f / NN);
    float var = g_colsumsq[t] * (1.0f / NN) - mu * mu;
    var = fmaxf(var, 0.f);
    float a = g[t] * rsqrtf(var + BN_EPS);
    g_alpha[t] = a;
    g_beta[t] = bt[t] - mu * a;
}

// Wfold[k,j] = alpha[k]*W[k,j]; bconst[j] = sum_k beta[k]*W[k,j]
// one block per output column j, K threads reduce
__global__ void fold_kernel(const float* __restrict__ W, int K, int Nn) {
    int j = blockIdx.x;
    int k = threadIdx.x;   // K threads (256)
    __shared__ float red[256];
    float bc = 0.f;
    if (k < K) {
        float w = W[k * Nn + j];
        g_Wfold[k * Nn + j] = g_alpha[k] * w;
        bc = g_beta[k] * w;
    }
    red[k] = bc;
    __syncthreads();
    for (int off = 128; off > 0; off >>= 1) {
        if (k < off) red[k] += red[k + off];
        __syncthreads();
    }
    if (k == 0) g_bconst[j] = red[0];
}

// ---------------- pooling ----------------
__global__ void counts_kernel(const int* __restrict__ batch) {
    int i = blockIdx.x * blockDim.x + threadIdx.x;
    if (i < NN) atomicAdd(&g_counts[batch[i]], 1);
}

__global__ void pool_kernel(const float* __restrict__ h,
                            const int* __restrict__ batch) {
    const int t = threadIdx.x;   // 128
    const int CH = 128;
    int n0 = blockIdx.x * CH;
    int n1 = min(n0 + CH, NN);
    int cur = batch[n0];
    float acc = 0.f;
    for (int n = n0; n < n1; n++) {
        int gr = batch[n];
        if (gr != cur) {
            atomicAdd(&g_pool[cur * 128 + t], acc);
            acc = 0.f;
            cur = gr;
        }
        acc += h[(size_t)n * 128 + t];
    }
    atomicAdd(&g_pool[cur * 128 + t], acc);
}

__global__ void finalize_kernel(float* __restrict__ out) {
    int gr = blockIdx.x, t = threadIdx.x;
    float c = fmaxf((float)g_counts[gr], 1.0f);
    out[gr * 128 + t] = g_alpha[t] * (g_pool[gr * 128 + t] / c) + g_beta[t];
}

// ---------------- launch ----------------
extern "C" void kernel_launch(void* const* d_in, const int* in_sizes, int n_in,
                              void* d_out, int out_size) {
    const float* x = (const float*)d_in[0];
    const int* ei = (const int*)d_in[1];      // int32 (JAX x64 disabled)
    const int* batch = (const int*)d_in[2];   // int32
    const float* W1 = (const float*)d_in[3];
    const float* b1 = (const float*)d_in[4];
    const float* g1 = (const float*)d_in[5];
    const float* bt1 = (const float*)d_in[6];
    const float* W2 = (const float*)d_in[7];
    const float* b2 = (const float*)d_in[8];
    const float* g2 = (const float*)d_in[9];
    const float* bt2 = (const float*)d_in[10];
    const float* W3 = (const float*)d_in[11];
    const float* b3 = (const float*)d_in[12];
    const float* g3 = (const float*)d_in[13];
    const float* bt3 = (const float*)d_in[14];
    const float* W4 = (const float*)d_in[15];
    const float* b4 = (const float*)d_in[16];
    const float* g4 = (const float*)d_in[17];
    const float* bt4 = (const float*)d_in[18];
    float* out = (float*)d_out;

    float* bufA; cudaGetSymbolAddress((void**)&bufA, g_bufA);
    float* bufB; cudaGetSymbolAddress((void**)&bufB, g_bufB);
    float* Wfold; cudaGetSymbolAddress((void**)&Wfold, g_Wfold);
    float* bconst; cudaGetSymbolAddress((void**)&bconst, g_bconst);
    float* zerovec; cudaGetSymbolAddress((void**)&zerovec, g_zerovec);

    // graph structure (recomputed every call; same work each call)
    copy_x_kernel<<<(NN * 128 + 255) / 256, 256>>>(x);
    zero_misc_kernel<<<(NN + 255) / 256, 256>>>();
    deg_kernel<<<(NE + 255) / 256, 256>>>(ei);
    prep_kernel<<<(NN + 255) / 256, 256>>>();
    scan_kernel<<<1, 1024>>>();
    scatter_kernel<<<(NE + 255) / 256, 256>>>(ei);

    dim3 gemm_grid_256(2, NPAD / 128);
    dim3 gemm_grid_128(1, NPAD / 128);
    int agg_grid = (NN + 31) / 32;
    dim3 agg_block_256(64, 4);
    dim3 agg_block_128(32, 8);

    // ---- layer 1: K=128 -> 256 ----
    gemm_kernel<<<gemm_grid_256, 256>>>(bufA, W1, zerovec, bufB, 128, 256);
    zero_stats_kernel<<<1, 256>>>();
    agg_kernel<256><<<agg_grid, agg_block_256>>>(bufB, b1, bufA);
    stats_kernel<<<1, 256>>>(g1, bt1);
    fold_kernel<<<256, 256>>>(W2, 256, 256);

    // ---- layer 2: 256 -> 256 ----
    gemm_kernel<<<gemm_grid_256, 256>>>(bufA, Wfold, bconst, bufB, 256, 256);
    zero_stats_kernel<<<1, 256>>>();
    agg_kernel<256><<<agg_grid, agg_block_256>>>(bufB, b2, bufA);
    stats_kernel<<<1, 256>>>(g2, bt2);
    fold_kernel<<<256, 256>>>(W3, 256, 256);

    // ---- layer 3: 256 -> 256 ----
    gemm_kernel<<<gemm_grid_256, 256>>>(bufA, Wfold, bconst, bufB, 256, 256);
    zero_stats_kernel<<<1, 256>>>();
    agg_kernel<256><<<agg_grid, agg_block_256>>>(bufB, b3, bufA);
    stats_kernel<<<1, 256>>>(g3, bt3);
    fold_kernel<<<128, 256>>>(W4, 256, 128);

    // ---- layer 4: 256 -> 128 ----
    gemm_kernel<<<gemm_grid_128, 256>>>(bufA, Wfold, bconst, bufB, 256, 128);
    zero_stats_kernel<<<1, 256>>>();
    agg_kernel<128><<<agg_grid, agg_block_128>>>(bufB, b4, bufA);
    stats_kernel<<<1, 128>>>(g4, bt4);

    // ---- pooling ----
    counts_kernel<<<(NN + 255) / 256, 256>>>(batch);
    pool_kernel<<<(NN + 127) / 128, 128>>>(bufA, batch);
    finalize_kernel<<<NG, 128>>>(out);
    (void)in_sizes; (void)n_in; (void)out_size;
}

// round 6
// speedup vs baseline: 1.4781x; 1.0124x over previous
#include <cuda_runtime.h>

// Problem constants (fixed by the dataset)
#define NN   50000
#define NE   800000
#define NG   64
#define NPAD 50048            // multiple of 128 for unguarded GEMM
#define NEG_SLOPE 0.01f
#define BN_EPS    1e-5f

// ---------------- scratch (static __device__, no allocation) ----------------
__device__ __align__(16) float g_bufA[NPAD * 256];
__device__ __align__(16) float g_bufB[NPAD * 256];
__device__ __align__(16) int   g_csrsrc[NE];
__device__ __align__(16) float g_csrnorm[NE];
__device__ __align__(16) int   g_rowptr[NN + 4];
__device__ __align__(16) int   g_deg[NN];
__device__ __align__(16) int   g_fill[NN];
__device__ __align__(16) float g_dinv[NN];
__device__ __align__(16) float g_selfnorm[NN];
__device__ __align__(16) float g_colsum[256];
__device__ __align__(16) float g_colsumsq[256];
__device__ __align__(16) float g_alpha[256];
__device__ __align__(16) float g_beta[256];
__device__ __align__(16) float g_Wfold[256 * 256];
__device__ __align__(16) float g_bconst[256];
__device__ __align__(16) float g_zerovec[256];     // never written -> stays 0
__device__ __align__(16) float g_pool[NG * 128];
__device__ __align__(16) int   g_counts[NG];

// ---------------- small utility kernels ----------------
__global__ void copy_x_kernel(const float* __restrict__ x) {
    int i = blockIdx.x * blockDim.x + threadIdx.x;
    if (i < NN * 128) g_bufA[i] = x[i];
}

__global__ void zero_misc_kernel() {
    int i = blockIdx.x * blockDim.x + threadIdx.x;
    if (i < NN) { g_deg[i] = 0; g_fill[i] = 0; }
    if (i < NG * 128) g_pool[i] = 0.f;
    if (i < NG) g_counts[i] = 0;
}

__global__ void zero_stats_kernel() {
    int t = threadIdx.x;
    g_colsum[t] = 0.f;
    g_colsumsq[t] = 0.f;
}

// edge_index is int32 (JAX x64 disabled downcasts int64 -> int32)
__global__ void deg_kernel(const int* __restrict__ ei) {
    int e = blockIdx.x * blockDim.x + threadIdx.x;
    if (e < NE) atomicAdd(&g_deg[ei[NE + e]], 1);  // dst row
}

__global__ void prep_kernel() {
    int i = blockIdx.x * blockDim.x + threadIdx.x;
    if (i < NN) {
        float d = (float)(g_deg[i] + 1);
        g_dinv[i] = rsqrtf(d);
        g_selfnorm[i] = 1.0f / d;
    }
}

// exclusive scan of g_deg -> g_rowptr (single block, 1024 threads)
__global__ void scan_kernel() {
    __shared__ int sh[1024];
    __shared__ int base_s;
    int tid = threadIdx.x;
    if (tid == 0) base_s = 0;
    __syncthreads();
    for (int start = 0; start < NN; start += 1024) {
        int i = start + tid;
        int v = (i < NN) ? g_deg[i] : 0;
        sh[tid] = v;
        __syncthreads();
        for (int off = 1; off < 1024; off <<= 1) {
            int add = (tid >= off) ? sh[tid - off] : 0;
            __syncthreads();
            sh[tid] += add;
            __syncthreads();
        }
        if (i < NN) g_rowptr[i] = base_s + sh[tid] - v;
        __syncthreads();
        if (tid == 0) base_s += sh[1023];
        __syncthreads();
    }
    if (tid == 0) g_rowptr[NN] = base_s;
}

__global__ void scatter_kernel(const int* __restrict__ ei) {
    int e = blockIdx.x * blockDim.x + threadIdx.x;
    if (e < NE) {
        int s = ei[e];
        int d = ei[NE + e];
        int p = g_rowptr[d] + atomicAdd(&g_fill[d], 1);
        g_csrsrc[p] = s;
        g_csrnorm[p] = g_dinv[s] * g_dinv[d];
    }
}

// ---------------- 3xTF32 tensor-core GEMM ----------------
// C[M,Nn] = A[M,K] @ W[K,Nn] + bconst, via mma.sync.m16n8k8 tf32 with
// hi/lo error compensation (precision ~fp32).
// Block 128x128, 8 warps (2x4), warp tile 64x32, BK=16.
__device__ __forceinline__ unsigned f2tf(float v) {
    unsigned u;
    asm("cvt.rna.tf32.f32 %0, %1;" : "=r"(u) : "f"(v));
    return u;
}

__device__ __forceinline__ void mma8(float* c, const unsigned* a,
                                     unsigned b0, unsigned b1) {
    asm volatile(
        "mma.sync.aligned.m16n8k8.row.col.f32.tf32.tf32.f32 "
        "{%0,%1,%2,%3}, {%4,%5,%6,%7}, {%8,%9}, {%0,%1,%2,%3};\n"
        : "+f"(c[0]), "+f"(c[1]), "+f"(c[2]), "+f"(c[3])
        : "r"(a[0]), "r"(a[1]), "r"(a[2]), "r"(a[3]), "r"(b0), "r"(b1));
}

#define SMS 137   // smem row stride (137 % 32 == 9): conflict-light

__global__ __launch_bounds__(256, 2)
void gemm_tf32_kernel(const float* __restrict__ A, const float* __restrict__ W,
                      const float* __restrict__ bconst, float* __restrict__ C,
                      int K, int Nn) {
    __shared__ unsigned Ah[16 * SMS];
    __shared__ unsigned Al[16 * SMS];
    __shared__ unsigned Bh[16 * SMS];
    __shared__ unsigned Bl[16 * SMS];

    const int tid = threadIdx.x;
    const int lane = tid & 31;
    const int w = tid >> 5;
    const int wm = w >> 2;            // 0..1
    const int wn = w & 3;             // 0..3
    const int q = lane >> 2;          // 0..7
    const int r4 = lane & 3;          // 0..3

    const float* Ab = A + (size_t)blockIdx.y * 128 * K;
    const float* Wb = W + blockIdx.x * 128;
    float* Cb = C + (size_t)blockIdx.y * 128 * Nn + blockIdx.x * 128;

    float acc[4][4][4];
#pragma unroll
    for (int mi = 0; mi < 4; mi++)
#pragma unroll
        for (int ni = 0; ni < 4; ni++)
#pragma unroll
            for (int rr = 0; rr < 4; rr++) acc[mi][ni][rr] = 0.f;

    for (int k0 = 0; k0 < K; k0 += 16) {
        // ---- fill tiles (hi/lo split at store time) ----
#pragma unroll
        for (int i = 0; i < 8; i++) {
            int idx = i * 256 + tid;
            int r = idx >> 4, c = idx & 15;
            float v = Ab[(size_t)r * K + k0 + c];
            unsigned h = f2tf(v);
            Ah[c * SMS + r] = h;
            Al[c * SMS + r] = f2tf(v - __uint_as_float(h));
        }
#pragma unroll
        for (int i = 0; i < 8; i++) {
            int idx = i * 256 + tid;
            int kk = idx >> 7, n = idx & 127;
            float v = Wb[(size_t)(k0 + kk) * Nn + n];
            unsigned h = f2tf(v);
            Bh[kk * SMS + n] = h;
            Bl[kk * SMS + n] = f2tf(v - __uint_as_float(h));
        }
        __syncthreads();

#pragma unroll
        for (int ks = 0; ks < 2; ks++) {
            const int kbase = (ks * 8 + r4) * SMS;
            unsigned ah[4][4], al[4][4];
#pragma unroll
            for (int mi = 0; mi < 4; mi++) {
                int m0 = wm * 64 + mi * 16 + q;
                ah[mi][0] = Ah[kbase + m0];
                ah[mi][1] = Ah[kbase + m0 + 8];
                ah[mi][2] = Ah[kbase + 4 * SMS + m0];
                ah[mi][3] = Ah[kbase + 4 * SMS + m0 + 8];
                al[mi][0] = Al[kbase + m0];
                al[mi][1] = Al[kbase + m0 + 8];
                al[mi][2] = Al[kbase + 4 * SMS + m0];
                al[mi][3] = Al[kbase + 4 * SMS + m0 + 8];
            }
#pragma unroll
            for (int ni = 0; ni < 4; ni++) {
                int n0b = wn * 32 + ni * 8 + q;
                unsigned bh0 = Bh[kbase + n0b];
                unsigned bh1 = Bh[kbase + 4 * SMS + n0b];
                unsigned bl0 = Bl[kbase + n0b];
                unsigned bl1 = Bl[kbase + 4 * SMS + n0b];
#pragma unroll
                for (int mi = 0; mi < 4; mi++) {
                    mma8(acc[mi][ni], ah[mi], bh0, bh1);  // hi*hi
                    mma8(acc[mi][ni], al[mi], bh0, bh1);  // lo*hi
                    mma8(acc[mi][ni], ah[mi], bl0, bl1);  // hi*lo
                }
            }
        }
        __syncthreads();
    }

    // ---- epilogue: add bconst, store float2 pairs ----
#pragma unroll
    for (int ni = 0; ni < 4; ni++) {
        int ncol = wn * 32 + ni * 8 + 2 * r4;
        float bcx = bconst[blockIdx.x * 128 + ncol];
        float bcy = bconst[blockIdx.x * 128 + ncol + 1];
#pragma unroll
        for (int mi = 0; mi < 4; mi++) {
            int row0 = wm * 64 + mi * 16 + q;
            float2 v0 = make_float2(acc[mi][ni][0] + bcx, acc[mi][ni][1] + bcy);
            float2 v1 = make_float2(acc[mi][ni][2] + bcx, acc[mi][ni][3] + bcy);
            *(float2*)(Cb + (size_t)row0 * Nn + ncol) = v0;
            *(float2*)(Cb + (size_t)(row0 + 8) * Nn + ncol) = v1;
        }
    }
}

// ---------------- aggregation + bias + LeakyReLU + BN-stat partials --------
// float4-vectorized: block = (DO/4) x TY threads, 32 nodes per block.
template <int DO>
__global__ void agg_kernel(const float* __restrict__ hw,
                           const float* __restrict__ bias,
                           float* __restrict__ out) {
    const int TX = DO / 4;            // threads along features (64 or 32)
    const int TY = 256 / TX;          // node lanes (4 or 8)
    const int NPB = 32;
    const int tx = threadIdx.x;       // feature group
    const int ty = threadIdx.y;       // node lane
    const float4* hw4 = (const float4*)hw;
    float4* out4 = (float4*)out;

    __shared__ float ssum[DO];
    __shared__ float ssq[DO];
    {
        int lin = ty * TX + tx;
        if (lin < DO) { ssum[lin] = 0.f; ssq[lin] = 0.f; }
    }
    __syncthreads();

    float4 b4 = *(const float4*)(bias + 4 * tx);
    int n0 = blockIdx.x * NPB;
    int n1 = min(n0 + NPB, NN);

    float s0 = 0.f, s1 = 0.f, s2 = 0.f, s3 = 0.f;
    float q0 = 0.f, q1 = 0.f, q2 = 0.f, q3 = 0.f;

    for (int n = n0 + ty; n < n1; n += TY) {
        int e0 = g_rowptr[n], e1 = g_rowptr[n + 1];
        float4 acc = make_float4(0.f, 0.f, 0.f, 0.f);
        int e = e0;
        for (; e + 4 <= e1; e += 4) {
            int i0 = g_csrsrc[e],     i1 = g_csrsrc[e + 1];
            int i2 = g_csrsrc[e + 2], i3 = g_csrsrc[e + 3];
            float w0 = g_csrnorm[e],     w1 = g_csrnorm[e + 1];
            float w2 = g_csrnorm[e + 2], w3 = g_csrnorm[e + 3];
            float4 v0 = hw4[(size_t)i0 * TX + tx];
            float4 v1 = hw4[(size_t)i1 * TX + tx];
            float4 v2 = hw4[(size_t)i2 * TX + tx];
            float4 v3 = hw4[(size_t)i3 * TX + tx];
            acc.x = fmaf(v0.x, w0, acc.x); acc.y = fmaf(v0.y, w0, acc.y);
            acc.z = fmaf(v0.z, w0, acc.z); acc.w = fmaf(v0.w, w0, acc.w);
            acc.x = fmaf(v1.x, w1, acc.x); acc.y = fmaf(v1.y, w1, acc.y);
            acc.z = fmaf(v1.z, w1, acc.z); acc.w = fmaf(v1.w, w1, acc.w);
            acc.x = fmaf(v2.x, w2, acc.x); acc.y = fmaf(v2.y, w2, acc.y);
            acc.z = fmaf(v2.z, w2, acc.z); acc.w = fmaf(v2.w, w2, acc.w);
            acc.x = fmaf(v3.x, w3, acc.x); acc.y = fmaf(v3.y, w3, acc.y);
            acc.z = fmaf(v3.z, w3, acc.z); acc.w = fmaf(v3.w, w3, acc.w);
        }
        for (; e < e1; ++e) {
            int i = g_csrsrc[e];
            float w = g_csrnorm[e];
            float4 v = hw4[(size_t)i * TX + tx];
            acc.x = fmaf(v.x, w, acc.x); acc.y = fmaf(v.y, w, acc.y);
            acc.z = fmaf(v.z, w, acc.z); acc.w = fmaf(v.w, w, acc.w);
        }
        float sn = g_selfnorm[n];
        float4 hv = hw4[(size_t)n * TX + tx];
        float v0 = fmaf(hv.x, sn, acc.x) + b4.x;
        float v1 = fmaf(hv.y, sn, acc.y) + b4.y;
        float v2 = fmaf(hv.z, sn, acc.z) + b4.z;
        float v3 = fmaf(hv.w, sn, acc.w) + b4.w;
        v0 = (v0 > 0.f) ? v0 : NEG_SLOPE * v0;
        v1 = (v1 > 0.f) ? v1 : NEG_SLOPE * v1;
        v2 = (v2 > 0.f) ? v2 : NEG_SLOPE * v2;
        v3 = (v3 > 0.f) ? v3 : NEG_SLOPE * v3;
        out4[(size_t)n * TX + tx] = make_float4(v0, v1, v2, v3);
        s0 += v0; s1 += v1; s2 += v2; s3 += v3;
        q0 = fmaf(v0, v0, q0); q1 = fmaf(v1, v1, q1);
        q2 = fmaf(v2, v2, q2); q3 = fmaf(v3, v3, q3);
    }

    atomicAdd(&ssum[4 * tx + 0], s0);
    atomicAdd(&ssum[4 * tx + 1], s1);
    atomicAdd(&ssum[4 * tx + 2], s2);
    atomicAdd(&ssum[4 * tx + 3], s3);
    atomicAdd(&ssq[4 * tx + 0], q0);
    atomicAdd(&ssq[4 * tx + 1], q1);
    atomicAdd(&ssq[4 * tx + 2], q2);
    atomicAdd(&ssq[4 * tx + 3], q3);
    __syncthreads();
    {
        int lin = ty * TX + tx;
        if (lin < DO) {
            atomicAdd(&g_colsum[lin], ssum[lin]);
            atomicAdd(&g_colsumsq[lin], ssq[lin]);
        }
    }
}

// stats + reset (ready for next layer / next replay)
__global__ void stats_kernel(const float* __restrict__ g,
                             const float* __restrict__ bt, int DO) {
    int t = threadIdx.x;   // 256
    if (t < DO) {
        float mu = g_colsum[t] * (1.0f / NN);
        float var = g_colsumsq[t] * (1.0f / NN) - mu * mu;
        var = fmaxf(var, 0.f);
        float a = g[t] * rsqrtf(var + BN_EPS);
        g_alpha[t] = a;
        g_beta[t] = bt[t] - mu * a;
    }
    g_colsum[t] = 0.f;
    g_colsumsq[t] = 0.f;
}

// Wfold[k,j] = alpha[k]*W[k,j]; bconst[j] = sum_k beta[k]*W[k,j]
// one block per output column j, K threads reduce
__global__ void fold_kernel(const float* __restrict__ W, int K, int Nn) {
    int j = blockIdx.x;
    int k = threadIdx.x;   // 256
    __shared__ float red[256];
    float bc = 0.f;
    if (k < K) {
        float w = W[k * Nn + j];
        g_Wfold[k * Nn + j] = g_alpha[k] * w;
        bc = g_beta[k] * w;
    }
    red[k] = bc;
    __syncthreads();
    for (int off = 128; off > 0; off >>= 1) {
        if (k < off) red[k] += red[k + off];
        __syncthreads();
    }
    if (k == 0) g_bconst[j] = red[0];
}

// ---------------- pooling ----------------
__global__ void counts_kernel(const int* __restrict__ batch) {
    int i = blockIdx.x * blockDim.x + threadIdx.x;
    if (i < NN) atomicAdd(&g_counts[batch[i]], 1);
}

__global__ void pool_kernel(const float* __restrict__ h,
                            const int* __restrict__ batch) {
    const int t = threadIdx.x;   // 128
    const int CH = 128;
    int n0 = blockIdx.x * CH;
    int n1 = min(n0 + CH, NN);
    int cur = batch[n0];
    float acc = 0.f;
    for (int n = n0; n < n1; n++) {
        int gr = batch[n];
        if (gr != cur) {
            atomicAdd(&g_pool[cur * 128 + t], acc);
            acc = 0.f;
            cur = gr;
        }
        acc += h[(size_t)n * 128 + t];
    }
    atomicAdd(&g_pool[cur * 128 + t], acc);
}

__global__ void finalize_kernel(float* __restrict__ out) {
    int gr = blockIdx.x, t = threadIdx.x;
    float c = fmaxf((float)g_counts[gr], 1.0f);
    out[gr * 128 + t] = g_alpha[t] * (g_pool[gr * 128 + t] / c) + g_beta[t];
}

// ---------------- launch ----------------
extern "C" void kernel_launch(void* const* d_in, const int* in_sizes, int n_in,
                              void* d_out, int out_size) {
    const float* x = (const float*)d_in[0];
    const int* ei = (const int*)d_in[1];      // int32 (JAX x64 disabled)
    const int* batch = (const int*)d_in[2];   // int32
    const float* W1 = (const float*)d_in[3];
    const float* b1 = (const float*)d_in[4];
    const float* g1 = (const float*)d_in[5];
    const float* bt1 = (const float*)d_in[6];
    const float* W2 = (const float*)d_in[7];
    const float* b2 = (const float*)d_in[8];
    const float* g2 = (const float*)d_in[9];
    const float* bt2 = (const float*)d_in[10];
    const float* W3 = (const float*)d_in[11];
    const float* b3 = (const float*)d_in[12];
    const float* g3 = (const float*)d_in[13];
    const float* bt3 = (const float*)d_in[14];
    const float* W4 = (const float*)d_in[15];
    const float* b4 = (const float*)d_in[16];
    const float* g4 = (const float*)d_in[17];
    const float* bt4 = (const float*)d_in[18];
    float* out = (float*)d_out;

    float* bufA; cudaGetSymbolAddress((void**)&bufA, g_bufA);
    float* bufB; cudaGetSymbolAddress((void**)&bufB, g_bufB);
    float* Wfold; cudaGetSymbolAddress((void**)&Wfold, g_Wfold);
    float* bconst; cudaGetSymbolAddress((void**)&bconst, g_bconst);
    float* zerovec; cudaGetSymbolAddress((void**)&zerovec, g_zerovec);

    // graph structure (recomputed every call; same work each call)
    copy_x_kernel<<<(NN * 128 + 255) / 256, 256>>>(x);
    zero_misc_kernel<<<(NN + 255) / 256, 256>>>();
    zero_stats_kernel<<<1, 256>>>();
    deg_kernel<<<(NE + 255) / 256, 256>>>(ei);
    prep_kernel<<<(NN + 255) / 256, 256>>>();
    scan_kernel<<<1, 1024>>>();
    scatter_kernel<<<(NE + 255) / 256, 256>>>(ei);

    dim3 gemm_grid_256(2, NPAD / 128);
    dim3 gemm_grid_128(1, NPAD / 128);
    int agg_grid = (NN + 31) / 32;
    dim3 agg_block_256(64, 4);
    dim3 agg_block_128(32, 8);

    // ---- layer 1: K=128 -> 256 ----
    gemm_tf32_kernel<<<gemm_grid_256, 256>>>(bufA, W1, zerovec, bufB, 128, 256);
    agg_kernel<256><<<agg_grid, agg_block_256>>>(bufB, b1, bufA);
    stats_kernel<<<1, 256>>>(g1, bt1, 256);
    fold_kernel<<<256, 256>>>(W2, 256, 256);

    // ---- layer 2: 256 -> 256 ----
    gemm_tf32_kernel<<<gemm_grid_256, 256>>>(bufA, Wfold, bconst, bufB, 256, 256);
    agg_kernel<256><<<agg_grid, agg_block_256>>>(bufB, b2, bufA);
    stats_kernel<<<1, 256>>>(g2, bt2, 256);
    fold_kernel<<<256, 256>>>(W3, 256, 256);

    // ---- layer 3: 256 -> 256 ----
    gemm_tf32_kernel<<<gemm_grid_256, 256>>>(bufA, Wfold, bconst, bufB, 256, 256);
    agg_kernel<256><<<agg_grid, agg_block_256>>>(bufB, b3, bufA);
    stats_kernel<<<1, 256>>>(g3, bt3, 256);
    fold_kernel<<<128, 256>>>(W4, 256, 128);

    // ---- layer 4: 256 -> 128 ----
    gemm_tf32_kernel<<<gemm_grid_128, 256>>>(bufA, Wfold, bconst, bufB, 256, 128);
    agg_kernel<128><<<agg_grid, agg_block_128>>>(bufB, b4, bufA);
    stats_kernel<<<1, 256>>>(g4, bt4, 128);

    // ---- pooling ----
    counts_kernel<<<(NN + 255) / 256, 256>>>(batch);
    pool_kernel<<<(NN + 127) / 128, 128>>>(bufA, batch);
    finalize_kernel<<<NG, 128>>>(out);
    (void)in_sizes; (void)n_in; (void)out_size;
}

// round 9
// speedup vs baseline: 1.5896x; 1.0754x over previous
#include <cuda_runtime.h>

// Problem constants (fixed by the dataset)
#define NN   50000
#define NE   800000
#define NG   64
#define NPAD 50048            // multiple of 128 for unguarded GEMM
#define NEG_SLOPE 0.01f
#define BN_EPS    1e-5f
#define NSB  196              // scan blocks: ceil(50000/256)

// ---------------- scratch (static __device__, no allocation) ----------------
__device__ __align__(16) float g_bufA[NPAD * 256];
__device__ __align__(16) float g_bufB[NPAD * 256];
__device__ __align__(16) int   g_csrsrc[NE];
__device__ __align__(16) float g_csrnorm[NE];
__device__ __align__(16) int   g_rowptr[NN + 4];
__device__ __align__(16) int   g_deg[NN];
__device__ __align__(16) int   g_fill[NN];
__device__ __align__(16) float g_dinv[NN];
__device__ __align__(16) float g_selfnorm[NN];
__device__ __align__(16) int   g_blocksum[256];
__device__ __align__(16) int   g_blockoff[256];
__device__ __align__(16) float g_colsum[256];
__device__ __align__(16) float g_colsumsq[256];
__device__ __align__(16) float g_alpha[256];
__device__ __align__(16) float g_beta[256];
__device__ __align__(16) float g_Wfold[256 * 256];
__device__ __align__(16) float g_bconst[256];
__device__ __align__(16) float g_zerovec[256];     // never written -> stays 0
__device__ __align__(16) float g_pool[NG * 128];
__device__ __align__(16) int   g_counts[NG];

// ---------------- small utility kernels ----------------
__global__ void copy_x_kernel(const float* __restrict__ x) {
    int i = blockIdx.x * blockDim.x + threadIdx.x;
    if (i < NN * 128) g_bufA[i] = x[i];
}

__global__ void zero_misc_kernel() {
    int i = blockIdx.x * blockDim.x + threadIdx.x;
    if (i < NN) { g_deg[i] = 0; g_fill[i] = 0; }
    if (i < NG * 128) g_pool[i] = 0.f;
    if (i < NG) g_counts[i] = 0;
}

__global__ void zero_stats_kernel() {
    int t = threadIdx.x;
    g_colsum[t] = 0.f;
    g_colsumsq[t] = 0.f;
}

// edge_index is int32 (JAX x64 disabled downcasts int64 -> int32)
__global__ void deg_kernel(const int* __restrict__ ei) {
    int e = blockIdx.x * blockDim.x + threadIdx.x;
    if (e < NE) atomicAdd(&g_deg[ei[NE + e]], 1);  // dst row
}

// ---------------- parallel 3-stage exclusive scan of g_deg -> g_rowptr -----
// stage 1: per-block inclusive scan of 256 degrees; write block-local
// exclusive values + block sums. Also computes dinv/selfnorm (fused prep).
__global__ void scan1_kernel() {
    __shared__ int sh[256];
    int b = blockIdx.x, t = threadIdx.x;
    int i = b * 256 + t;
    int v = (i < NN) ? g_deg[i] : 0;
    if (i < NN) {
        float d = (float)(v + 1);
        g_dinv[i] = rsqrtf(d);
        g_selfnorm[i] = 1.0f / d;
    }
    sh[t] = v;
    __syncthreads();
#pragma unroll
    for (int off = 1; off < 256; off <<= 1) {
        int add = (t >= off) ? sh[t - off] : 0;
        __syncthreads();
        sh[t] += add;
        __syncthreads();
    }
    if (i < NN) g_rowptr[i] = sh[t] - v;     // block-local exclusive
    if (t == 255) g_blocksum[b] = sh[255];
}

// stage 2: single block scans NSB block sums (exclusive)
__global__ void scan2_kernel() {
    __shared__ int sh[256];
    int t = threadIdx.x;
    int v = (t < NSB) ? g_blocksum[t] : 0;
    sh[t] = v;
    __syncthreads();
#pragma unroll
    for (int off = 1; off < 256; off <<= 1) {
        int add = (t >= off) ? sh[t - off] : 0;
        __syncthreads();
        sh[t] += add;
        __syncthreads();
    }
    if (t < NSB) g_blockoff[t] = sh[t] - v;
}

// stage 3: add block offsets; total is statically NE
__global__ void scan3_kernel() {
    int i = blockIdx.x * blockDim.x + threadIdx.x;
    if (i < NN) g_rowptr[i] += g_blockoff[i >> 8];
    if (i == 0) g_rowptr[NN] = NE;
}

__global__ void scatter_kernel(const int* __restrict__ ei) {
    int e = blockIdx.x * blockDim.x + threadIdx.x;
    if (e < NE) {
        int s = ei[e];
        int d = ei[NE + e];
        int p = g_rowptr[d] + atomicAdd(&g_fill[d], 1);
        g_csrsrc[p] = s;
        g_csrnorm[p] = g_dinv[s] * g_dinv[d];
    }
}

// ---------------- 3xTF32 tensor-core GEMM ----------------
// C[M,Nn] = A[M,K] @ W[K,Nn] + bconst, via mma.sync.m16n8k8 tf32 with
// hi/lo error compensation (precision ~fp32).
// Block 128x128, 8 warps (2x4), warp tile 64x32, BK=16.
__device__ __forceinline__ unsigned f2tf(float v) {
    unsigned u;
    asm("cvt.rna.tf32.f32 %0, %1;" : "=r"(u) : "f"(v));
    return u;
}

__device__ __forceinline__ void mma8(float* c, const unsigned* a,
                                     unsigned b0, unsigned b1) {
    asm volatile(
        "mma.sync.aligned.m16n8k8.row.col.f32.tf32.tf32.f32 "
        "{%0,%1,%2,%3}, {%4,%5,%6,%7}, {%8,%9}, {%0,%1,%2,%3};\n"
        : "+f"(c[0]), "+f"(c[1]), "+f"(c[2]), "+f"(c[3])
        : "r"(a[0]), "r"(a[1]), "r"(a[2]), "r"(a[3]), "r"(b0), "r"(b1));
}

#define SMS 137   // smem row stride (137 % 32 == 9): conflict-light

__global__ __launch_bounds__(256, 2)
void gemm_tf32_kernel(const float* __restrict__ A, const float* __restrict__ W,
                      const float* __restrict__ bconst, float* __restrict__ C,
                      int K, int Nn) {
    __shared__ unsigned Ah[16 * SMS];
    __shared__ unsigned Al[16 * SMS];
    __shared__ unsigned Bh[16 * SMS];
    __shared__ unsigned Bl[16 * SMS];

    const int tid = threadIdx.x;
    const int lane = tid & 31;
    const int w = tid >> 5;
    const int wm = w >> 2;            // 0..1
    const int wn = w & 3;             // 0..3
    const int q = lane >> 2;          // 0..7
    const int r4 = lane & 3;          // 0..3

    const float* Ab = A + (size_t)blockIdx.y * 128 * K;
    const float* Wb = W + blockIdx.x * 128;
    float* Cb = C + (size_t)blockIdx.y * 128 * Nn + blockIdx.x * 128;

    float acc[4][4][4];
#pragma unroll
    for (int mi = 0; mi < 4; mi++)
#pragma unroll
        for (int ni = 0; ni < 4; ni++)
#pragma unroll
            for (int rr = 0; rr < 4; rr++) acc[mi][ni][rr] = 0.f;

    for (int k0 = 0; k0 < K; k0 += 16) {
        // ---- fill tiles (hi/lo split at store time) ----
#pragma unroll
        for (int i = 0; i < 8; i++) {
            int idx = i * 256 + tid;
            int r = idx >> 4, c = idx & 15;
            float v = Ab[(size_t)r * K + k0 + c];
            unsigned h = f2tf(v);
            Ah[c * SMS + r] = h;
            Al[c * SMS + r] = f2tf(v - __uint_as_float(h));
        }
#pragma unroll
        for (int i = 0; i < 8; i++) {
            int idx = i * 256 + tid;
            int kk = idx >> 7, n = idx & 127;
            float v = Wb[(size_t)(k0 + kk) * Nn + n];
            unsigned h = f2tf(v);
            Bh[kk * SMS + n] = h;
            Bl[kk * SMS + n] = f2tf(v - __uint_as_float(h));
        }
        __syncthreads();

#pragma unroll
        for (int ks = 0; ks < 2; ks++) {
            const int kbase = (ks * 8 + r4) * SMS;
            unsigned ah[4][4], al[4][4];
#pragma unroll
            for (int mi = 0; mi < 4; mi++) {
                int m0 = wm * 64 + mi * 16 + q;
                ah[mi][0] = Ah[kbase + m0];
                ah[mi][1] = Ah[kbase + m0 + 8];
                ah[mi][2] = Ah[kbase + 4 * SMS + m0];
                ah[mi][3] = Ah[kbase + 4 * SMS + m0 + 8];
                al[mi][0] = Al[kbase + m0];
                al[mi][1] = Al[kbase + m0 + 8];
                al[mi][2] = Al[kbase + 4 * SMS + m0];
                al[mi][3] = Al[kbase + 4 * SMS + m0 + 8];
            }
#pragma unroll
            for (int ni = 0; ni < 4; ni++) {
                int n0b = wn * 32 + ni * 8 + q;
                unsigned bh0 = Bh[kbase + n0b];
                unsigned bh1 = Bh[kbase + 4 * SMS + n0b];
                unsigned bl0 = Bl[kbase + n0b];
                unsigned bl1 = Bl[kbase + 4 * SMS + n0b];
#pragma unroll
                for (int mi = 0; mi < 4; mi++) {
                    mma8(acc[mi][ni], ah[mi], bh0, bh1);  // hi*hi
                    mma8(acc[mi][ni], al[mi], bh0, bh1);  // lo*hi
                    mma8(acc[mi][ni], ah[mi], bl0, bl1);  // hi*lo
                }
            }
        }
        __syncthreads();
    }

    // ---- epilogue: add bconst, store float2 pairs ----
#pragma unroll
    for (int ni = 0; ni < 4; ni++) {
        int ncol = wn * 32 + ni * 8 + 2 * r4;
        float bcx = bconst[blockIdx.x * 128 + ncol];
        float bcy = bconst[blockIdx.x * 128 + ncol + 1];
#pragma unroll
        for (int mi = 0; mi < 4; mi++) {
            int row0 = wm * 64 + mi * 16 + q;
            float2 v0 = make_float2(acc[mi][ni][0] + bcx, acc[mi][ni][1] + bcy);
            float2 v1 = make_float2(acc[mi][ni][2] + bcx, acc[mi][ni][3] + bcy);
            *(float2*)(Cb + (size_t)row0 * Nn + ncol) = v0;
            *(float2*)(Cb + (size_t)(row0 + 8) * Nn + ncol) = v1;
        }
    }
}

// ---------------- aggregation + bias + LeakyReLU + BN-stat partials --------
// float4-vectorized: block = (DO/4) x TY threads, 32 nodes per block.
template <int DO>
__global__ void agg_kernel(const float* __restrict__ hw,
                           const float* __restrict__ bias,
                           float* __restrict__ out) {
    const int TX = DO / 4;            // threads along features (64 or 32)
    const int TY = 256 / TX;          // node lanes (4 or 8)
    const int NPB = 32;
    const int tx = threadIdx.x;       // feature group
    const int ty = threadIdx.y;       // node lane
    const float4* hw4 = (const float4*)hw;
    float4* out4 = (float4*)out;

    __shared__ float ssum[DO];
    __shared__ float ssq[DO];
    {
        int lin = ty * TX + tx;
        if (lin < DO) { ssum[lin] = 0.f; ssq[lin] = 0.f; }
    }
    __syncthreads();

    float4 b4 = *(const float4*)(bias + 4 * tx);
    int n0 = blockIdx.x * NPB;
    int n1 = min(n0 + NPB, NN);

    float s0 = 0.f, s1 = 0.f, s2 = 0.f, s3 = 0.f;
    float q0 = 0.f, q1 = 0.f, q2 = 0.f, q3 = 0.f;

    for (int n = n0 + ty; n < n1; n += TY) {
        int e0 = g_rowptr[n], e1 = g_rowptr[n + 1];
        float4 acc = make_float4(0.f, 0.f, 0.f, 0.f);
        int e = e0;
        for (; e + 4 <= e1; e += 4) {
            int i0 = g_csrsrc[e],     i1 = g_csrsrc[e + 1];
            int i2 = g_csrsrc[e + 2], i3 = g_csrsrc[e + 3];
            float w0 = g_csrnorm[e],     w1 = g_csrnorm[e + 1];
            float w2 = g_csrnorm[e + 2], w3 = g_csrnorm[e + 3];
            float4 v0 = hw4[(size_t)i0 * TX + tx];
            float4 v1 = hw4[(size_t)i1 * TX + tx];
            float4 v2 = hw4[(size_t)i2 * TX + tx];
            float4 v3 = hw4[(size_t)i3 * TX + tx];
            acc.x = fmaf(v0.x, w0, acc.x); acc.y = fmaf(v0.y, w0, acc.y);
            acc.z = fmaf(v0.z, w0, acc.z); acc.w = fmaf(v0.w, w0, acc.w);
            acc.x = fmaf(v1.x, w1, acc.x); acc.y = fmaf(v1.y, w1, acc.y);
            acc.z = fmaf(v1.z, w1, acc.z); acc.w = fmaf(v1.w, w1, acc.w);
            acc.x = fmaf(v2.x, w2, acc.x); acc.y = fmaf(v2.y, w2, acc.y);
            acc.z = fmaf(v2.z, w2, acc.z); acc.w = fmaf(v2.w, w2, acc.w);
            acc.x = fmaf(v3.x, w3, acc.x); acc.y = fmaf(v3.y, w3, acc.y);
            acc.z = fmaf(v3.z, w3, acc.z); acc.w = fmaf(v3.w, w3, acc.w);
        }
        for (; e < e1; ++e) {
            int i = g_csrsrc[e];
            float w = g_csrnorm[e];
            float4 v = hw4[(size_t)i * TX + tx];
            acc.x = fmaf(v.x, w, acc.x); acc.y = fmaf(v.y, w, acc.y);
            acc.z = fmaf(v.z, w, acc.z); acc.w = fmaf(v.w, w, acc.w);
        }
        float sn = g_selfnorm[n];
        float4 hv = hw4[(size_t)n * TX + tx];
        float v0 = fmaf(hv.x, sn, acc.x) + b4.x;
        float v1 = fmaf(hv.y, sn, acc.y) + b4.y;
        float v2 = fmaf(hv.z, sn, acc.z) + b4.z;
        float v3 = fmaf(hv.w, sn, acc.w) + b4.w;
        v0 = (v0 > 0.f) ? v0 : NEG_SLOPE * v0;
        v1 = (v1 > 0.f) ? v1 : NEG_SLOPE * v1;
        v2 = (v2 > 0.f) ? v2 : NEG_SLOPE * v2;
        v3 = (v3 > 0.f) ? v3 : NEG_SLOPE * v3;
        out4[(size_t)n * TX + tx] = make_float4(v0, v1, v2, v3);
        s0 += v0; s1 += v1; s2 += v2; s3 += v3;
        q0 = fmaf(v0, v0, q0); q1 = fmaf(v1, v1, q1);
        q2 = fmaf(v2, v2, q2); q3 = fmaf(v3, v3, q3);
    }

    atomicAdd(&ssum[4 * tx + 0], s0);
    atomicAdd(&ssum[4 * tx + 1], s1);
    atomicAdd(&ssum[4 * tx + 2], s2);
    atomicAdd(&ssum[4 * tx + 3], s3);
    atomicAdd(&ssq[4 * tx + 0], q0);
    atomicAdd(&ssq[4 * tx + 1], q1);
    atomicAdd(&ssq[4 * tx + 2], q2);
    atomicAdd(&ssq[4 * tx + 3], q3);
    __syncthreads();
    {
        int lin = ty * TX + tx;
        if (lin < DO) {
            atomicAdd(&g_colsum[lin], ssum[lin]);
            atomicAdd(&g_colsumsq[lin], ssq[lin]);
        }
    }
}

// stats + reset (ready for next layer / next replay)
__global__ void stats_kernel(const float* __restrict__ g,
                             const float* __restrict__ bt, int DO) {
    int t = threadIdx.x;   // 256
    if (t < DO) {
        float mu = g_colsum[t] * (1.0f / NN);
        float var = g_colsumsq[t] * (1.0f / NN) - mu * mu;
        var = fmaxf(var, 0.f);
        float a = g[t] * rsqrtf(var + BN_EPS);
        g_alpha[t] = a;
        g_beta[t] = bt[t] - mu * a;
    }
    g_colsum[t] = 0.f;
    g_colsumsq[t] = 0.f;
}

// Wfold[k,j] = alpha[k]*W[k,j]; bconst[j] = sum_k beta[k]*W[k,j]
// one block per output column j, K threads reduce
__global__ void fold_kernel(const float* __restrict__ W, int K, int Nn) {
    int j = blockIdx.x;
    int k = threadIdx.x;   // 256
    __shared__ float red[256];
    float bc = 0.f;
    if (k < K) {
        float w = W[k * Nn + j];
        g_Wfold[k * Nn + j] = g_alpha[k] * w;
        bc = g_beta[k] * w;
    }
    red[k] = bc;
    __syncthreads();
    for (int off = 128; off > 0; off >>= 1) {
        if (k < off) red[k] += red[k + off];
        __syncthreads();
    }
    if (k == 0) g_bconst[j] = red[0];
}

// ---------------- pooling ----------------
__global__ void counts_kernel(const int* __restrict__ batch) {
    int i = blockIdx.x * blockDim.x + threadIdx.x;
    if (i < NN) atomicAdd(&g_counts[batch[i]], 1);
}

__global__ void pool_kernel(const float* __restrict__ h,
                            const int* __restrict__ batch) {
    const int t = threadIdx.x;   // 128
    const int CH = 128;
    int n0 = blockIdx.x * CH;
    int n1 = min(n0 + CH, NN);
    int cur = batch[n0];
    float acc = 0.f;
    for (int n = n0; n < n1; n++) {
        int gr = batch[n];
        if (gr != cur) {
            atomicAdd(&g_pool[cur * 128 + t], acc);
            acc = 0.f;
            cur = gr;
        }
        acc += h[(size_t)n * 128 + t];
    }
    atomicAdd(&g_pool[cur * 128 + t], acc);
}

__global__ void finalize_kernel(float* __restrict__ out) {
    int gr = blockIdx.x, t = threadIdx.x;
    float c = fmaxf((float)g_counts[gr], 1.0f);
    out[gr * 128 + t] = g_alpha[t] * (g_pool[gr * 128 + t] / c) + g_beta[t];
}

// ---------------- launch ----------------
extern "C" void kernel_launch(void* const* d_in, const int* in_sizes, int n_in,
                              void* d_out, int out_size) {
    const float* x = (const float*)d_in[0];
    const int* ei = (const int*)d_in[1];      // int32 (JAX x64 disabled)
    const int* batch = (const int*)d_in[2];   // int32
    const float* W1 = (const float*)d_in[3];
    const float* b1 = (const float*)d_in[4];
    const float* g1 = (const float*)d_in[5];
    const float* bt1 = (const float*)d_in[6];
    const float* W2 = (const float*)d_in[7];
    const float* b2 = (const float*)d_in[8];
    const float* g2 = (const float*)d_in[9];
    const float* bt2 = (const float*)d_in[10];
    const float* W3 = (const float*)d_in[11];
    const float* b3 = (const float*)d_in[12];
    const float* g3 = (const float*)d_in[13];
    const float* bt3 = (const float*)d_in[14];
    const float* W4 = (const float*)d_in[15];
    const float* b4 = (const float*)d_in[16];
    const float* g4 = (const float*)d_in[17];
    const float* bt4 = (const float*)d_in[18];
    float* out = (float*)d_out;

    float* bufA; cudaGetSymbolAddress((void**)&bufA, g_bufA);
    float* bufB; cudaGetSymbolAddress((void**)&bufB, g_bufB);
    float* Wfold; cudaGetSymbolAddress((void**)&Wfold, g_Wfold);
    float* bconst; cudaGetSymbolAddress((void**)&bconst, g_bconst);
    float* zerovec; cudaGetSymbolAddress((void**)&zerovec, g_zerovec);

    // graph structure (recomputed every call; same work each call)
    copy_x_kernel<<<(NN * 128 + 255) / 256, 256>>>(x);
    zero_misc_kernel<<<(NN + 255) / 256, 256>>>();
    zero_stats_kernel<<<1, 256>>>();
    deg_kernel<<<(NE + 255) / 256, 256>>>(ei);
    scan1_kernel<<<NSB, 256>>>();
    scan2_kernel<<<1, 256>>>();
    scan3_kernel<<<(NN + 255) / 256, 256>>>();
    scatter_kernel<<<(NE + 255) / 256, 256>>>(ei);

    dim3 gemm_grid_256(2, NPAD / 128);
    dim3 gemm_grid_128(1, NPAD / 128);
    int agg_grid = (NN + 31) / 32;
    dim3 agg_block_256(64, 4);
    dim3 agg_block_128(32, 8);

    // ---- layer 1: K=128 -> 256 ----
    gemm_tf32_kernel<<<gemm_grid_256, 256>>>(bufA, W1, zerovec, bufB, 128, 256);
    agg_kernel<256><<<agg_grid, agg_block_256>>>(bufB, b1, bufA);
    stats_kernel<<<1, 256>>>(g1, bt1, 256);
    fold_kernel<<<256, 256>>>(W2, 256, 256);

    // ---- layer 2: 256 -> 256 ----
    gemm_tf32_kernel<<<gemm_grid_256, 256>>>(bufA, Wfold, bconst, bufB, 256, 256);
    agg_kernel<256><<<agg_grid, agg_block_256>>>(bufB, b2, bufA);
    stats_kernel<<<1, 256>>>(g2, bt2, 256);
    fold_kernel<<<256, 256>>>(W3, 256, 256);

    // ---- layer 3: 256 -> 256 ----
    gemm_tf32_kernel<<<gemm_grid_256, 256>>>(bufA, Wfold, bconst, bufB, 256, 256);
    agg_kernel<256><<<agg_grid, agg_block_256>>>(bufB, b3, bufA);
    stats_kernel<<<1, 256>>>(g3, bt3, 256);
    fold_kernel<<<128, 256>>>(W4, 256, 128);

    // ---- layer 4: 256 -> 128 ----
    gemm_tf32_kernel<<<gemm_grid_128, 256>>>(bufA, Wfold, bconst, bufB, 256, 128);
    agg_kernel<128><<<agg_grid, agg_block_128>>>(bufB, b4, bufA);
    stats_kernel<<<1, 256>>>(g4, bt4, 128);

    // ---- pooling ----
    counts_kernel<<<(NN + 255) / 256, 256>>>(batch);
    pool_kernel<<<(NN + 127) / 128, 128>>>(bufA, batch);
    finalize_kernel<<<NG, 128>>>(out);
    (void)in_sizes; (void)n_in; (void)out_size;
}